// round 1
// baseline (speedup 1.0000x reference)
#include <cuda_runtime.h>
#include <cuda_bf16.h>

// Problem dims (fixed by the dataset)
#define BB 2
#define DD 10
#define HH 512
#define WW 512

// Output layout: coords (B, 3, D, H, W) followed by y (B, D, H, W)
// coords idx = (((b*3 + k)*DD + d)*HH + h)*WW + w
// y      idx = B*3*D*H*W + ((b*DD + d)*HH + h)*WW + w

__global__ __launch_bounds__(256)
void quadinterp3d_kernel(const float* __restrict__ x, float* __restrict__ out) {
    int gid = blockIdx.x * blockDim.x + threadIdx.x;
    // total threads = B*D*H*(W/4) = 2*10*512*128 = 1,310,720
    int w4 = gid & 127;            // W/4 = 128
    int h  = (gid >> 7) & 511;     // H = 512
    int t  = gid >> 16;            // 0..19  (B*D)
    int d  = t % DD;
    int b  = t / DD;
    int w0 = w4 << 2;

    // Load 9 rows (3 d-planes x 3 h-rows), 6 consecutive w values each:
    // v[r][0] = x[w0-1] (clamped), v[r][1..4] = x[w0..w0+3], v[r][5] = x[w0+4] (clamped)
    float v[9][6];
    #pragma unroll
    for (int dz = 0; dz < 3; dz++) {
        int zz = min(max(d + dz - 1, 0), DD - 1);
        #pragma unroll
        for (int dy = 0; dy < 3; dy++) {
            int yy = min(max(h + dy - 1, 0), HH - 1);
            const float* row = x + (((size_t)(b * DD + zz) * HH + yy) * WW);
            int r = dz * 3 + dy;
            float4 m4 = *reinterpret_cast<const float4*>(row + w0);
            v[r][0] = __ldg(row + max(w0 - 1, 0));
            v[r][1] = m4.x; v[r][2] = m4.y; v[r][3] = m4.z; v[r][4] = m4.w;
            v[r][5] = __ldg(row + min(w0 + 4, WW - 1));
        }
    }

    float yv[4], ck0[4], ck1[4], ck2[4];

    #pragma unroll
    for (int j = 0; j < 4; j++) {
        // n[dz][dy][k] = v[dz*3+dy][j+k]; k: 0=w-1, 1=w, 2=w+1
        const float cc = v[4][j + 1];

        // nmax = max over 26 neighbors, then max with 0
        float nmax = 0.0f;
        #pragma unroll
        for (int r = 0; r < 9; r++) {
            #pragma unroll
            for (int k = 0; k < 3; k++) {
                if (r == 4 && k == 1) continue;
                nmax = fmaxf(nmax, v[r][j + k]);
            }
        }
        const bool m = cc > nmax;

        float dx0 = 0.0f, dx1 = 0.0f, dx2 = 0.0f;
        float yval = cc;

        if (m) {
            const float gx = 0.5f * (v[4][j + 2] - v[4][j]);
            const float gy = 0.5f * (v[5][j + 1] - v[3][j + 1]);
            const float gs = 0.5f * (v[7][j + 1] - v[1][j + 1]);

            const float dxx = v[4][j] + v[4][j + 2] - 2.0f * cc;
            const float dyy = v[3][j + 1] + v[5][j + 1] - 2.0f * cc;
            const float dss = v[1][j + 1] + v[7][j + 1] - 2.0f * cc;
            const float dxy = 0.25f * (v[3][j] + v[5][j + 2] - v[5][j] - v[3][j + 2]);
            const float dys = 0.25f * (v[0][j + 1] + v[8][j + 1] - v[6][j + 1] - v[2][j + 1]);
            const float dxs = 0.25f * (v[1][j] + v[7][j + 2] - v[7][j] - v[1][j + 2]);

            // Symmetric Hessian (Rm perturbation ~1e-7 omitted; below tolerance)
            const float h00 = dxx, h01 = dxy, h02 = dxs;
            const float h10 = dxy, h11 = dyy, h12 = dys;
            const float h20 = dxs, h21 = dys, h22 = dss;
            const float b0 = gx, b1 = gy, b2 = gs;

            const float c00 = h11 * h22 - h12 * h21;
            const float c01 = h10 * h22 - h12 * h20;
            const float c02 = h10 * h21 - h11 * h20;
            const float det = h00 * c00 - h01 * c01 + h02 * c02;

            const float t1 = b1 * h22 - h12 * b2;
            const float t2 = b1 * h21 - h11 * b2;
            const float t3 = h10 * b2 - b1 * h20;

            const float inv = 1.0f / det;
            const float sx = (b0 * c00 - h01 * t1 + h02 * t2) * inv;
            const float sy = (h00 * t1 - b0 * c01 + h02 * t3) * inv;
            const float ss = (h00 * (h11 * b2 - h21 * b1) - h01 * t3 + b0 * c02) * inv;

            dx0 = -sx; dx1 = -sy; dx2 = -ss;

            const float far = fmaxf(fmaxf(fabsf(dx0), fabsf(dx1)), fabsf(dx2));
            if (far > 0.7f) { dx0 = 0.0f; dx1 = 0.0f; dx2 = 0.0f; }

            yval = cc + 0.5f * (gx * dx0 + gy * dx1 + gs * dx2) + 10.0f;
        }

        yv[j]  = yval;
        ck0[j] = (float)d + dx2;
        ck1[j] = (float)h + dx1;
        ck2[j] = (float)(w0 + j) + dx0;
    }

    // Coalesced float4 stores
    const size_t plane = (size_t)DD * HH * WW;                 // 2,621,440
    const size_t inner = ((size_t)d * HH + h) * WW + w0;
    float4* o0 = reinterpret_cast<float4*>(out + (size_t)(b * 3 + 0) * plane + inner);
    float4* o1 = reinterpret_cast<float4*>(out + (size_t)(b * 3 + 1) * plane + inner);
    float4* o2 = reinterpret_cast<float4*>(out + (size_t)(b * 3 + 2) * plane + inner);
    float4* oy = reinterpret_cast<float4*>(out + (size_t)BB * 3 * plane
                                               + (size_t)b * plane + inner);
    *o0 = make_float4(ck0[0], ck0[1], ck0[2], ck0[3]);
    *o1 = make_float4(ck1[0], ck1[1], ck1[2], ck1[3]);
    *o2 = make_float4(ck2[0], ck2[1], ck2[2], ck2[3]);
    *oy = make_float4(yv[0], yv[1], yv[2], yv[3]);
}

extern "C" void kernel_launch(void* const* d_in, const int* in_sizes, int n_in,
                              void* d_out, int out_size) {
    const float* x = (const float*)d_in[0];
    float* out = (float*)d_out;
    const int total_threads = BB * DD * HH * (WW / 4);   // 1,310,720
    const int block = 256;
    const int grid = total_threads / block;              // 5,120
    quadinterp3d_kernel<<<grid, block>>>(x, out);
}